// round 15
// baseline (speedup 1.0000x reference)
#include <cuda_runtime.h>

#define B_ 2
#define N_ 4096
#define M_ 4096
#define K_ 2048
#define NN 8192          // B_*N_ flattened points
#define KTOP 50
#define UWSL 1024        // per-warp E-bucket slice (floats)

static __device__ unsigned g_min_pg[B_*N_];   // min over gt for each pred
static __device__ unsigned g_min_gp[B_*M_];   // min over pred for each gt
static __device__ unsigned g_min_cov[B_*K_];  // min over pred for each partial
static __device__ double   g_acc[8];          // 0:cham1 1:cham2 2:cov 3:emd 4:unif 5:spread 6:rep
static __device__ float4   g_pts4[NN];        // packed pred points for uniformity
static __device__ float    g_rows1[NN];       // per-row sum of top-50 distances
static __device__ float    g_rows2[NN];       // per-row sum of top-50 squared distances
static __device__ float    g_sortP[3*NN];
static __device__ float    g_sortG[3*NN];

// ---------------------------------------------------------------- helpers
__device__ __forceinline__ void block_add_to_acc(float v, int slot) {
    for (int o = 16; o; o >>= 1) v += __shfl_xor_sync(0xFFFFFFFFu, v, o);
    __shared__ float sw[32];
    int lane = threadIdx.x & 31, wid = threadIdx.x >> 5;
    if (lane == 0) sw[wid] = v;
    __syncthreads();
    if (threadIdx.x == 0) {
        float s = 0.f;
        int nw = (blockDim.x + 31) >> 5;
        for (int w = 0; w < nw; w++) s += sw[w];
        atomicAdd(&g_acc[slot], (double)s);
    }
}

__device__ __forceinline__ unsigned* min_sel(int which) {
    return which == 0 ? g_min_pg : (which == 1 ? g_min_gp : g_min_cov);
}

// warp-collective (all lanes get result): first bin of 256-bin hist h where
// cumulative count >= target, plus cumulative strictly below that bin.
__device__ __forceinline__ void warp_find(const unsigned* __restrict__ h, int target,
                                          int lane, unsigned& bin_out, unsigned& below_out) {
    unsigned v8[8], loc = 0;
#pragma unroll
    for (int b = 0; b < 8; b++) { v8[b] = h[lane*8 + b]; loc += v8[b]; }
    unsigned pre = loc;
    for (int o = 1; o < 32; o <<= 1) {
        unsigned t = __shfl_up_sync(0xFFFFFFFFu, pre, o);
        if (lane >= o) pre += t;
    }
    unsigned cum = pre - loc;          // exclusive prefix
    int myBin = 256; unsigned myBelow = 0;
#pragma unroll
    for (int b = 0; b < 8; b++) {
        unsigned nb = cum + v8[b];
        if ((int)nb >= target && myBin == 256) { myBin = lane*8 + b; myBelow = cum; }
        cum = nb;
    }
    for (int o = 16; o; o >>= 1) {
        int ob = __shfl_xor_sync(0xFFFFFFFFu, myBin, o);
        unsigned obl = __shfl_xor_sync(0xFFFFFFFFu, myBelow, o);
        if (ob < myBin) { myBin = ob; myBelow = obl; }
    }
    bin_out = (unsigned)myBin; below_out = myBelow;
}

// ---------------------------------------------------------------- init + pack (fused)
__global__ void initpack_kernel(const float* __restrict__ pred) {
    int i = blockIdx.x * 256 + threadIdx.x;
    if (i < B_*N_) g_min_pg[i]  = 0x7F800000u;
    if (i < B_*M_) g_min_gp[i]  = 0x7F800000u;
    if (i < B_*K_) g_min_cov[i] = 0x7F800000u;
    if (i < 8)     g_acc[i] = 0.0;
    if (i < NN)
        g_pts4[i] = make_float4(pred[3*i], pred[3*i+1], pred[3*i+2], 0.f);
}

// ---------------------------------------------------------------- row-min pairwise sq dist
__global__ void rowmin_kernel(const float* __restrict__ A, const float* __restrict__ Bp,
                              int nA, int nB, int chunk, int which) {
    __shared__ float sb[384];
    int b = blockIdx.z;
    const float* Ab = A  + (size_t)b * nA * 3;
    const float* Bb = Bp + ((size_t)b * nB + (size_t)blockIdx.y * chunk) * 3;
    int i0 = blockIdx.x * 256 + threadIdx.x;
    int i1 = i0 + 128;
    float ax0 = Ab[3*i0], ay0 = Ab[3*i0+1], az0 = Ab[3*i0+2];
    float ax1 = Ab[3*i1], ay1 = Ab[3*i1+1], az1 = Ab[3*i1+2];
    float best0 = __int_as_float(0x7F800000);
    float best1 = best0;
    for (int t = 0; t < chunk; t += 128) {
        __syncthreads();
        const float* src = Bb + 3*t;
        sb[threadIdx.x]       = src[threadIdx.x];
        sb[threadIdx.x + 128] = src[threadIdx.x + 128];
        sb[threadIdx.x + 256] = src[threadIdx.x + 256];
        __syncthreads();
#pragma unroll 8
        for (int j = 0; j < 128; j++) {
            float qx = sb[3*j], qy = sb[3*j+1], qz = sb[3*j+2];
            float dx0 = ax0 - qx, dy0 = ay0 - qy, dz0 = az0 - qz;
            float dx1 = ax1 - qx, dy1 = ay1 - qy, dz1 = az1 - qz;
            float dd0 = fmaf(dx0, dx0, fmaf(dy0, dy0, dz0*dz0));
            float dd1 = fmaf(dx1, dx1, fmaf(dy1, dy1, dz1*dz1));
            best0 = fminf(best0, dd0);
            best1 = fminf(best1, dd1);
        }
    }
    unsigned* dst = min_sel(which);
    atomicMin(&dst[b*nA + i0], __float_as_uint(best0));
    atomicMin(&dst[b*nA + i1], __float_as_uint(best1));
}

// ---------------------------------------------------------------- fused sum-of-mins
__global__ void summin_all_kernel() {
    int blk = blockIdx.x;
    float v;
    if (blk < 32) {
        v = __uint_as_float(g_min_pg[blk*256 + threadIdx.x]);
        block_add_to_acc(v, 0);
    } else if (blk < 64) {
        v = __uint_as_float(g_min_gp[(blk-32)*256 + threadIdx.x]);
        block_add_to_acc(v, 1);
    } else {
        v = sqrtf(__uint_as_float(g_min_cov[(blk-64)*256 + threadIdx.x]));
        block_add_to_acc(v, 2);
    }
}

// ---------------------------------------------------------------- EMD: bitonic column sort
__global__ void emd_sort_kernel(const float* __restrict__ pred, const float* __restrict__ gt) {
    __shared__ float a[NN];
    int which = blockIdx.x;           // 0..5
    int c = which % 3;
    const float* src = (which < 3) ? pred : gt;
    float* dst = (which < 3) ? (g_sortP + c*NN) : (g_sortG + c*NN);
    int tid = threadIdx.x;
    for (int i = tid; i < NN; i += 1024) a[i] = src[3*i + c];
    __syncthreads();
    for (int k = 2; k <= NN; k <<= 1)
        for (int j = k >> 1; j > 0; j >>= 1) {
            for (int i = tid; i < NN; i += 1024) {
                int ixj = i ^ j;
                if (ixj > i) {
                    float x = a[i], y = a[ixj];
                    bool up = ((i & k) == 0);
                    if ((x > y) == up) { a[i] = y; a[ixj] = x; }
                }
            }
            __syncthreads();
        }
    for (int i = tid; i < NN; i += 1024) dst[i] = a[i];
}

__global__ void emd_diff_kernel() {
    int i = blockIdx.x * 256 + threadIdx.x;
    float v = 0.f;
    if (i < 3*NN) { float d = g_sortP[i] - g_sortG[i]; v = d*d; }
    block_add_to_acc(v, 3);
}

// ---------------------------------------------------------------- uniformity: per-row 50-NN std
// WARP-AUTONOMOUS: one warp owns one row vs all 8192 points (2 rows/warp).
// No __syncthreads; per-warp private histogram/slice; warp_find once per row.
// Pass 1: distances + exponent hist -> E. Pass 2: recompute distances
// (identical fmaf => identical bits), accumulate bins<E, collect bucket E into
// own slice + fine mantissa hist (reusing hist buffer) -> F. Pass 3: sweep
// slice, micro-rank boundary fine bin. One writer per row -> direct stores.
__global__ void __launch_bounds__(128) uniformity_kernel() {
    __shared__ unsigned s_hist[4*256];
    __shared__ float    s_slice[4*UWSL];
    __shared__ float    s_bnd[4*64];
    __shared__ unsigned s_cnt[4], s_bcnt[4];
    int tid = threadIdx.x, lane = tid & 31, wid = tid >> 5;
    unsigned lmask = (1u << lane) - 1u;
    unsigned* hist  = s_hist  + wid*256;
    float*    slice = s_slice + wid*UWSL;
    float*    bnd   = s_bnd   + wid*64;

    for (int r = 0; r < 2; r++) {
        int row = (blockIdx.x * 4 + wid) * 2 + r;
        float4 p = g_pts4[row];
#pragma unroll
        for (int z = 0; z < 8; z++) hist[z*32 + lane] = 0;
        if (lane == 0) { s_cnt[wid] = 0; s_bcnt[wid] = 0; }
        __syncwarp();

        // pass 1: distances + exponent histogram (match-aggregated, warp-private)
        for (int j = lane; j < NN; j += 32) {
            float4 q = g_pts4[j];
            float dx = p.x - q.x, dy = p.y - q.y, dz = p.z - q.z;
            float v = fmaf(dx, dx, fmaf(dy, dy, dz*dz));
            unsigned bin = __float_as_uint(v) >> 23;
            unsigned mask = __match_any_sync(0xFFFFFFFFu, bin);
            if ((mask & lmask) == 0) atomicAdd(&hist[bin], (unsigned)__popc(mask));
        }
        __syncwarp();
        unsigned E, below;
        warp_find(hist, KTOP, lane, E, below);
        int m = KTOP - (int)below;             // needed from bucket E (>=1)
        __syncwarp();
        // reuse hist as fine (mantissa) histogram
#pragma unroll
        for (int z = 0; z < 8; z++) hist[z*32 + lane] = 0;
        __syncwarp();

        // pass 2: recompute; bins<E accumulate; bin==E -> slice + fine hist
        float t1 = 0.f, t2 = 0.f;
        for (int j = lane; j < NN; j += 32) {
            float4 q = g_pts4[j];
            float dx = p.x - q.x, dy = p.y - q.y, dz = p.z - q.z;
            float v = fmaf(dx, dx, fmaf(dy, dy, dz*dz));
            unsigned bin = __float_as_uint(v) >> 23;
            if (bin < E) { t1 += sqrtf(v); t2 += v; }
            else if (bin == E) {
                unsigned off = atomicAdd(&s_cnt[wid], 1u);
                if (off < UWSL) slice[off] = v;
                atomicAdd(&hist[(__float_as_uint(v) >> 15) & 0xFFu], 1u);
            }
        }
        __syncwarp();
        unsigned F, belowF;
        warp_find(hist, m, lane, F, belowF);
        int m2 = m - (int)belowF;              // needed from fine bin F (>=1)
        // pass 3: sweep own slice
        unsigned cE = min(s_cnt[wid], (unsigned)UWSL);
        for (unsigned j = lane; j < cE; j += 32) {
            float v = slice[j];
            unsigned key = (__float_as_uint(v) >> 15) & 0xFFu;
            if (key < F) { t1 += sqrtf(v); t2 += v; }
            else if (key == F) {
                unsigned pos = atomicAdd(&s_bcnt[wid], 1u);
                if (pos < 64) bnd[pos] = v;
            }
        }
        __syncwarp();
        int cF = (int)min(s_bcnt[wid], 64u);
        // micro-rank boundary fine bin, take m2 smallest (index tiebreak; ties
        // are equal values so the selected multiset is exact)
        for (int j = lane; j < cF; j += 32) {
            float v = bnd[j];
            int rank = 0;
            for (int k2 = 0; k2 < cF; k2++) {
                float w = bnd[k2];
                rank += (w < v) || (w == v && k2 < j);
            }
            if (rank < m2) { t1 += sqrtf(v); t2 += v; }
        }
        // warp reduce; single writer per row -> direct store
        for (int o = 16; o; o >>= 1) {
            t1 += __shfl_xor_sync(0xFFFFFFFFu, t1, o);
            t2 += __shfl_xor_sync(0xFFFFFFFFu, t2, o);
        }
        if (lane == 0) { g_rows1[row] = t1; g_rows2[row] = t2; }
        __syncwarp();
    }
}

// ---------------------------------------------------------------- uniformity finish (parallel std)
__global__ void unif_finish_kernel() {
    int i = blockIdx.x * 256 + threadIdx.x;
    float stdv = 0.f;
    if (i < NN) {
        double s1 = (double)g_rows1[i], s2 = (double)g_rows2[i];
        double mean = s1 / 49.0;
        double var = (s2 - 49.0*mean*mean) / 48.0;
        if (var < 0.0) var = 0.0;
        stdv = (float)sqrt(var);
    }
    block_add_to_acc(stdv, 4);
}

// ---------------------------------------------------------------- spread + repulsion (fused)
__global__ void spreadrep_kernel(const float* __restrict__ pred,
                                 const int* __restrict__ sidx) {
    int tid = threadIdx.x;
    if (blockIdx.x < 6) {
        int b = blockIdx.x / 3, c = blockIdx.x % 3;
        const float* p = pred + (size_t)b * N_ * 3 + c;
        double s1 = 0.0, s2 = 0.0;
        for (int i = tid; i < N_; i += 256) {
            double x = (double)p[3*i];
            s1 += x; s2 += x*x;
        }
        for (int o = 16; o; o >>= 1) {
            s1 += __shfl_xor_sync(0xFFFFFFFFu, s1, o);
            s2 += __shfl_xor_sync(0xFFFFFFFFu, s2, o);
        }
        __shared__ double sw1[8], sw2[8];
        int lane = tid & 31, wid = tid >> 5;
        if (lane == 0) { sw1[wid] = s1; sw2[wid] = s2; }
        __syncthreads();
        if (tid == 0) {
            double a = 0, bb = 0;
            for (int w = 0; w < 8; w++) { a += sw1[w]; bb += sw2[w]; }
            double mean = a / (double)N_;
            double var = (bb - (double)N_ * mean * mean) / (double)(N_ - 1);
            if (var < 0.0) var = 0.0;
            atomicAdd(&g_acc[5], sqrt(var));
        }
    } else {
        // NOTE: sample_idx arrives as int32 (JAX x64 disabled downcasts astype(int64)).
        __shared__ float sp[200*3];
        for (int s = tid; s < 200; s += 256) {
            int b = s / 100, k = s % 100;
            int idx = sidx[k];
            if (idx < 0) idx = 0;
            if (idx >= N_) idx = N_ - 1;
            const float* src = pred + ((size_t)b * N_ + (size_t)idx) * 3;
            sp[3*s] = src[0]; sp[3*s+1] = src[1]; sp[3*s+2] = src[2];
        }
        __syncthreads();
        float sum = 0.f;
        for (int t = tid; t < 2*100*100; t += 256) {
            int b = t / 10000, rem = t % 10000, i = rem / 100, j = rem % 100;
            if (i != j) {
                const float* pi = &sp[(b*100 + i)*3];
                const float* pj = &sp[(b*100 + j)*3];
                float dx = pi[0]-pj[0], dy = pi[1]-pj[1], dz = pi[2]-pj[2];
                float dd = fmaf(dx, dx, fmaf(dy, dy, dz*dz));
                float rr = 0.01f - sqrtf(dd);
                if (rr > 0.f) sum += rr;
            }
        }
        block_add_to_acc(sum, 6);
    }
}

// ---------------------------------------------------------------- finalize
__global__ void final_kernel(float* out) {
    double cham   = g_acc[0] / (double)(B_*N_) + g_acc[1] / (double)(B_*M_);
    double emd    = g_acc[3] / (double)(NN*3) * 0.1;
    double cov    = g_acc[2] / (double)(B_*K_) * 5.0;
    double unif   = g_acc[4] / (double)NN * 2.0;
    double sstd   = g_acc[5] / 6.0;
    double spread = 0.5 - sstd;
    spread = (spread > 0.0) ? spread * 10.0 : 0.0;
    double rep    = g_acc[6] / (double)(B_*100*100) * 5.0;
    out[0] = (float)(cham + emd + cov + unif + spread + rep);
}

// ---------------------------------------------------------------- launch
// Critical path (stream 0): initpack -> rowmin1,2 -> uniformity -> unif_finish -> final.
// Side chain (s2, hides under uniformity): EMD sort/diff, cov rowmin,
// summin (after evA guarantees rowmin1,2 done), spreadrep.
extern "C" void kernel_launch(void* const* d_in, const int* in_sizes, int n_in,
                              void* d_out, int out_size) {
    const float* pred    = (const float*)d_in[0];
    const float* gt      = (const float*)d_in[1];
    const float* partial = (const float*)d_in[2];
    const int*   sidx    = (const int*)d_in[3];
    float* out = (float*)d_out;

    static cudaStream_t s2 = 0;
    static cudaEvent_t  evRoot = 0, evA = 0, ev2 = 0;
    if (s2 == 0) {
        cudaStreamCreateWithFlags(&s2, cudaStreamNonBlocking);
        cudaEventCreateWithFlags(&evRoot, cudaEventDisableTiming);
        cudaEventCreateWithFlags(&evA, cudaEventDisableTiming);
        cudaEventCreateWithFlags(&ev2, cudaEventDisableTiming);
    }

    initpack_kernel<<<32, 256>>>(pred);                                           // 1
    cudaEventRecord(evRoot, 0);
    cudaStreamWaitEvent(s2, evRoot, 0);

    rowmin_kernel<<<dim3(N_/256, 16, B_), 128>>>(pred, gt,   N_, M_, M_/16, 0);   // 2
    rowmin_kernel<<<dim3(M_/256, 16, B_), 128>>>(gt,   pred, M_, N_, N_/16, 1);   // 3
    cudaEventRecord(evA, 0);
    uniformity_kernel<<<NN/8, 128>>>();                                           // 4 <- profiled

    emd_sort_kernel<<<6, 1024, 0, s2>>>(pred, gt);                                // s2
    emd_diff_kernel<<<(3*NN+255)/256, 256, 0, s2>>>();                            // s2
    rowmin_kernel<<<dim3(K_/256, 16, B_), 128, 0, s2>>>(partial, pred, K_, N_, N_/16, 2);
    cudaStreamWaitEvent(s2, evA, 0);
    summin_all_kernel<<<80, 256, 0, s2>>>();
    spreadrep_kernel<<<7, 256, 0, s2>>>(pred, sidx);
    cudaEventRecord(ev2, s2);

    unif_finish_kernel<<<32, 256>>>();

    cudaStreamWaitEvent(0, ev2, 0);
    final_kernel<<<1, 1>>>(out);
}

// round 16
// speedup vs baseline: 1.0907x; 1.0907x over previous
#include <cuda_runtime.h>

#define B_ 2
#define N_ 4096
#define M_ 4096
#define K_ 2048
#define NN 8192          // B_*N_ flattened points
#define KTOP 50
#define WSL 256          // per-warp E-bucket slice (floats)
#define UROWS 28         // rows per uniformity block (grid 293 ~ one 2-block wave)

static __device__ unsigned g_min_pg[B_*N_];   // min over gt for each pred
static __device__ unsigned g_min_gp[B_*M_];   // min over pred for each gt
static __device__ unsigned g_min_cov[B_*K_];  // min over pred for each partial
static __device__ double   g_acc[8];          // 0:cham1 1:cham2 2:cov 3:emd 4:unif 5:spread 6:rep
static __device__ float4   g_pts4[NN];        // packed pred points for uniformity
static __device__ float    g_rows1[NN];       // per-row sum of top-50 distances
static __device__ float    g_rows2[NN];       // per-row sum of top-50 squared distances
static __device__ float    g_sortP[3*NN];
static __device__ float    g_sortG[3*NN];

// ---------------------------------------------------------------- helpers
__device__ __forceinline__ void block_add_to_acc(float v, int slot) {
    for (int o = 16; o; o >>= 1) v += __shfl_xor_sync(0xFFFFFFFFu, v, o);
    __shared__ float sw[32];
    int lane = threadIdx.x & 31, wid = threadIdx.x >> 5;
    if (lane == 0) sw[wid] = v;
    __syncthreads();
    if (threadIdx.x == 0) {
        float s = 0.f;
        int nw = (blockDim.x + 31) >> 5;
        for (int w = 0; w < nw; w++) s += sw[w];
        atomicAdd(&g_acc[slot], (double)s);
    }
}

__device__ __forceinline__ unsigned* min_sel(int which) {
    return which == 0 ? g_min_pg : (which == 1 ? g_min_gp : g_min_cov);
}

// warp-collective (all lanes get result): first bin of 256-bin hist h where
// cumulative count >= target, plus cumulative strictly below that bin.
__device__ __forceinline__ void warp_find(const unsigned* __restrict__ h, int target,
                                          int lane, unsigned& bin_out, unsigned& below_out) {
    unsigned v8[8], loc = 0;
#pragma unroll
    for (int b = 0; b < 8; b++) { v8[b] = h[lane*8 + b]; loc += v8[b]; }
    unsigned pre = loc;
    for (int o = 1; o < 32; o <<= 1) {
        unsigned t = __shfl_up_sync(0xFFFFFFFFu, pre, o);
        if (lane >= o) pre += t;
    }
    unsigned cum = pre - loc;          // exclusive prefix
    int myBin = 256; unsigned myBelow = 0;
#pragma unroll
    for (int b = 0; b < 8; b++) {
        unsigned nb = cum + v8[b];
        if ((int)nb >= target && myBin == 256) { myBin = lane*8 + b; myBelow = cum; }
        cum = nb;
    }
    for (int o = 16; o; o >>= 1) {
        int ob = __shfl_xor_sync(0xFFFFFFFFu, myBin, o);
        unsigned obl = __shfl_xor_sync(0xFFFFFFFFu, myBelow, o);
        if (ob < myBin) { myBin = ob; myBelow = obl; }
    }
    bin_out = (unsigned)myBin; below_out = myBelow;
}

// ---------------------------------------------------------------- init + pack (fused)
__global__ void initpack_kernel(const float* __restrict__ pred) {
    int i = blockIdx.x * 256 + threadIdx.x;
    if (i < B_*N_) g_min_pg[i]  = 0x7F800000u;
    if (i < B_*M_) g_min_gp[i]  = 0x7F800000u;
    if (i < B_*K_) g_min_cov[i] = 0x7F800000u;
    if (i < 8)     g_acc[i] = 0.0;
    if (i < NN) {
        g_pts4[i] = make_float4(pred[3*i], pred[3*i+1], pred[3*i+2], 0.f);
        g_rows1[i] = 0.f;
        g_rows2[i] = 0.f;
    }
}

// ---------------------------------------------------------------- row-min pairwise sq dist
// Generic version (used for coverage on the side stream).
__global__ void rowmin_kernel(const float* __restrict__ A, const float* __restrict__ Bp,
                              int nA, int nB, int chunk, int which) {
    __shared__ float sb[384];
    int b = blockIdx.z;
    const float* Ab = A  + (size_t)b * nA * 3;
    const float* Bb = Bp + ((size_t)b * nB + (size_t)blockIdx.y * chunk) * 3;
    int i0 = blockIdx.x * 256 + threadIdx.x;
    int i1 = i0 + 128;
    float ax0 = Ab[3*i0], ay0 = Ab[3*i0+1], az0 = Ab[3*i0+2];
    float ax1 = Ab[3*i1], ay1 = Ab[3*i1+1], az1 = Ab[3*i1+2];
    float best0 = __int_as_float(0x7F800000);
    float best1 = best0;
    for (int t = 0; t < chunk; t += 128) {
        __syncthreads();
        const float* src = Bb + 3*t;
        sb[threadIdx.x]       = src[threadIdx.x];
        sb[threadIdx.x + 128] = src[threadIdx.x + 128];
        sb[threadIdx.x + 256] = src[threadIdx.x + 256];
        __syncthreads();
#pragma unroll 8
        for (int j = 0; j < 128; j++) {
            float qx = sb[3*j], qy = sb[3*j+1], qz = sb[3*j+2];
            float dx0 = ax0 - qx, dy0 = ay0 - qy, dz0 = az0 - qz;
            float dx1 = ax1 - qx, dy1 = ay1 - qy, dz1 = az1 - qz;
            float dd0 = fmaf(dx0, dx0, fmaf(dy0, dy0, dz0*dz0));
            float dd1 = fmaf(dx1, dx1, fmaf(dy1, dy1, dz1*dz1));
            best0 = fminf(best0, dd0);
            best1 = fminf(best1, dd1);
        }
    }
    unsigned* dst = min_sel(which);
    atomicMin(&dst[b*nA + i0], __float_as_uint(best0));
    atomicMin(&dst[b*nA + i1], __float_as_uint(best1));
}

// Merged big chamfer scans: z = batch + 2*direction (dir0: pred->gt, dir1: gt->pred).
__global__ void rowmin_big_kernel(const float* __restrict__ pred, const float* __restrict__ gt) {
    __shared__ float sb[384];
    int z = blockIdx.z;
    int b = z & 1, dir = z >> 1;
    const float* A  = dir ? gt : pred;
    const float* Bp = dir ? pred : gt;
    unsigned* dst   = dir ? g_min_gp : g_min_pg;
    const int chunk = N_ / 16;   // N_ == M_
    const float* Ab = A  + (size_t)b * N_ * 3;
    const float* Bb = Bp + ((size_t)b * N_ + (size_t)blockIdx.y * chunk) * 3;
    int i0 = blockIdx.x * 256 + threadIdx.x;
    int i1 = i0 + 128;
    float ax0 = Ab[3*i0], ay0 = Ab[3*i0+1], az0 = Ab[3*i0+2];
    float ax1 = Ab[3*i1], ay1 = Ab[3*i1+1], az1 = Ab[3*i1+2];
    float best0 = __int_as_float(0x7F800000);
    float best1 = best0;
    for (int t = 0; t < chunk; t += 128) {
        __syncthreads();
        const float* src = Bb + 3*t;
        sb[threadIdx.x]       = src[threadIdx.x];
        sb[threadIdx.x + 128] = src[threadIdx.x + 128];
        sb[threadIdx.x + 256] = src[threadIdx.x + 256];
        __syncthreads();
#pragma unroll 8
        for (int j = 0; j < 128; j++) {
            float qx = sb[3*j], qy = sb[3*j+1], qz = sb[3*j+2];
            float dx0 = ax0 - qx, dy0 = ay0 - qy, dz0 = az0 - qz;
            float dx1 = ax1 - qx, dy1 = ay1 - qy, dz1 = az1 - qz;
            float dd0 = fmaf(dx0, dx0, fmaf(dy0, dy0, dz0*dz0));
            float dd1 = fmaf(dx1, dx1, fmaf(dy1, dy1, dz1*dz1));
            best0 = fminf(best0, dd0);
            best1 = fminf(best1, dd1);
        }
    }
    atomicMin(&dst[b*N_ + i0], __float_as_uint(best0));
    atomicMin(&dst[b*N_ + i1], __float_as_uint(best1));
}

// ---------------------------------------------------------------- fused sum-of-mins
__global__ void summin_all_kernel() {
    int blk = blockIdx.x;
    float v;
    if (blk < 32) {
        v = __uint_as_float(g_min_pg[blk*256 + threadIdx.x]);
        block_add_to_acc(v, 0);
    } else if (blk < 64) {
        v = __uint_as_float(g_min_gp[(blk-32)*256 + threadIdx.x]);
        block_add_to_acc(v, 1);
    } else {
        v = sqrtf(__uint_as_float(g_min_cov[(blk-64)*256 + threadIdx.x]));
        block_add_to_acc(v, 2);
    }
}

// ---------------------------------------------------------------- EMD: bitonic column sort
__global__ void emd_sort_kernel(const float* __restrict__ pred, const float* __restrict__ gt) {
    __shared__ float a[NN];
    int which = blockIdx.x;           // 0..5
    int c = which % 3;
    const float* src = (which < 3) ? pred : gt;
    float* dst = (which < 3) ? (g_sortP + c*NN) : (g_sortG + c*NN);
    int tid = threadIdx.x;
    for (int i = tid; i < NN; i += 1024) a[i] = src[3*i + c];
    __syncthreads();
    for (int k = 2; k <= NN; k <<= 1)
        for (int j = k >> 1; j > 0; j >>= 1) {
            for (int i = tid; i < NN; i += 1024) {
                int ixj = i ^ j;
                if (ixj > i) {
                    float x = a[i], y = a[ixj];
                    bool up = ((i & k) == 0);
                    if ((x > y) == up) { a[i] = y; a[ixj] = x; }
                }
            }
            __syncthreads();
        }
    for (int i = tid; i < NN; i += 1024) dst[i] = a[i];
}

__global__ void emd_diff_kernel() {
    int i = blockIdx.x * 256 + threadIdx.x;
    float v = 0.f;
    if (i < 3*NN) { float d = g_sortP[i] - g_sortG[i]; v = d*d; }
    block_add_to_acc(v, 3);
}

// ---------------------------------------------------------------- uniformity: per-row 50-NN std
// (R12-proven shape) 512 threads, d[16]/thread, 2 blocks/SM. Exact top-50:
// shared exponent hist (match-aggregated) -> E; bucket-E gather via per-warp
// counters + fine mantissa hist -> F; micro-rank boundary bin. Shared state
// double-buffered by row parity -> the trailing barrier (old B5) is gone:
// set p's last reads precede row r+1's B4, so row r+2's zeroing can't race.
__global__ void __launch_bounds__(512, 2) uniformity_kernel() {
    __shared__ unsigned s_hist[2][256];
    __shared__ unsigned s_fine[2][256];
    __shared__ float    s_buf[16*WSL];       // per-warp E-bucket slices (warp-private)
    __shared__ float    s_buf2[2][64];       // boundary fine-bin members (tiny)
    __shared__ unsigned s_wcnt[2][16];
    __shared__ unsigned s_cnt2[2];
    int tid = threadIdx.x, lane = tid & 31, wid = tid >> 5;
    unsigned lmask = (1u << lane) - 1u;

    for (int r = 0; r < UROWS; r++) {
        int row = blockIdx.x * UROWS + r;
        if (row >= NN) break;              // uniform per block
        int p = r & 1;
        float4 pt = g_pts4[row];
        if (tid < 256) { s_hist[p][tid] = 0; s_fine[p][tid] = 0; }
        if (tid < 16) s_wcnt[p][tid] = 0;
        if (tid == 0) s_cnt2[p] = 0;
        __syncthreads();                                       // B1

        float d[16];
#pragma unroll
        for (int k = 0; k < 16; k++) {
            float4 q = g_pts4[k*512 + tid];
            float dx = pt.x - q.x, dy = pt.y - q.y, dz = pt.z - q.z;
            d[k] = fmaf(dx, dx, fmaf(dy, dy, dz*dz));
        }
        // exponent histogram (match-aggregated shared atomics)
#pragma unroll
        for (int k = 0; k < 16; k++) {
            unsigned bin = __float_as_uint(d[k]) >> 23;
            unsigned mask = __match_any_sync(0xFFFFFFFFu, bin);
            if ((mask & lmask) == 0)
                atomicAdd(&s_hist[p][bin], (unsigned)__popc(mask));
        }
        __syncthreads();                                       // B2
        unsigned E, below;
        warp_find(s_hist[p], KTOP, lane, E, below);            // all warps, redundant
        int m = KTOP - (int)below;                             // needed from bucket E (>=1)

        // gather: bins<E accumulate; bin==E (rare ~4%) -> own warp slice + fine hist
        float t1 = 0.f, t2 = 0.f;
#pragma unroll
        for (int k = 0; k < 16; k++) {
            float v = d[k];
            unsigned bin = __float_as_uint(v) >> 23;
            if (bin < E) { t1 += sqrtf(v); t2 += v; }
            else if (bin == E) {
                unsigned off = atomicAdd(&s_wcnt[p][wid], 1u);
                if (off < WSL) s_buf[wid*WSL + off] = v;
                atomicAdd(&s_fine[p][(__float_as_uint(v) >> 15) & 0xFFu], 1u);
            }
        }
        __syncthreads();                                       // B3
        unsigned F, belowF;
        warp_find(s_fine[p], m, lane, F, belowF);
        int m2 = m - (int)belowF;                              // needed from fine bin F (>=1)
        // sweep own slice
        unsigned myc = min(s_wcnt[p][wid], (unsigned)WSL);
        for (unsigned j = lane; j < myc; j += 32) {
            float v = s_buf[wid*WSL + j];
            unsigned key = (__float_as_uint(v) >> 15) & 0xFFu;
            if (key < F) { t1 += sqrtf(v); t2 += v; }
            else if (key == F) {
                unsigned pos = atomicAdd(&s_cnt2[p], 1u);
                if (pos < 64) s_buf2[p][pos] = v;
            }
        }
        __syncthreads();                                       // B4
        int cF = (int)min(s_cnt2[p], 64u);
        // micro-rank boundary fine bin, take the m2 smallest (index tiebreak;
        // ties are equal values so the selected multiset is exact)
        for (int j = tid; j < cF; j += 512) {
            float v = s_buf2[p][j];
            int rank = 0;
            for (int k2 = 0; k2 < cF; k2++) {
                float w = s_buf2[p][k2];
                rank += (w < v) || (w == v && k2 < j);
            }
            if (rank < m2) { t1 += sqrtf(v); t2 += v; }
        }
        // warp-reduce partials, one global float atomic pair per warp
        for (int o = 16; o; o >>= 1) {
            t1 += __shfl_xor_sync(0xFFFFFFFFu, t1, o);
            t2 += __shfl_xor_sync(0xFFFFFFFFu, t2, o);
        }
        if (lane == 0) {
            atomicAdd(&g_rows1[row], t1);
            atomicAdd(&g_rows2[row], t2);
        }
        // no trailing barrier: next row uses the other buffer set
    }
}

// ---------------------------------------------------------------- uniformity finish (parallel std)
__global__ void unif_finish_kernel() {
    int i = blockIdx.x * 256 + threadIdx.x;
    float stdv = 0.f;
    if (i < NN) {
        double s1 = (double)g_rows1[i], s2 = (double)g_rows2[i];
        double mean = s1 / 49.0;
        double var = (s2 - 49.0*mean*mean) / 48.0;
        if (var < 0.0) var = 0.0;
        stdv = (float)sqrt(var);
    }
    block_add_to_acc(stdv, 4);
}

// ---------------------------------------------------------------- spread + repulsion (fused)
__global__ void spreadrep_kernel(const float* __restrict__ pred,
                                 const int* __restrict__ sidx) {
    int tid = threadIdx.x;
    if (blockIdx.x < 6) {
        int b = blockIdx.x / 3, c = blockIdx.x % 3;
        const float* p = pred + (size_t)b * N_ * 3 + c;
        double s1 = 0.0, s2 = 0.0;
        for (int i = tid; i < N_; i += 256) {
            double x = (double)p[3*i];
            s1 += x; s2 += x*x;
        }
        for (int o = 16; o; o >>= 1) {
            s1 += __shfl_xor_sync(0xFFFFFFFFu, s1, o);
            s2 += __shfl_xor_sync(0xFFFFFFFFu, s2, o);
        }
        __shared__ double sw1[8], sw2[8];
        int lane = tid & 31, wid = tid >> 5;
        if (lane == 0) { sw1[wid] = s1; sw2[wid] = s2; }
        __syncthreads();
        if (tid == 0) {
            double a = 0, bb = 0;
            for (int w = 0; w < 8; w++) { a += sw1[w]; bb += sw2[w]; }
            double mean = a / (double)N_;
            double var = (bb - (double)N_ * mean * mean) / (double)(N_ - 1);
            if (var < 0.0) var = 0.0;
            atomicAdd(&g_acc[5], sqrt(var));
        }
    } else {
        // NOTE: sample_idx arrives as int32 (JAX x64 disabled downcasts astype(int64)).
        __shared__ float sp[200*3];
        for (int s = tid; s < 200; s += 256) {
            int b = s / 100, k = s % 100;
            int idx = sidx[k];
            if (idx < 0) idx = 0;
            if (idx >= N_) idx = N_ - 1;
            const float* src = pred + ((size_t)b * N_ + (size_t)idx) * 3;
            sp[3*s] = src[0]; sp[3*s+1] = src[1]; sp[3*s+2] = src[2];
        }
        __syncthreads();
        float sum = 0.f;
        for (int t = tid; t < 2*100*100; t += 256) {
            int b = t / 10000, rem = t % 10000, i = rem / 100, j = rem % 100;
            if (i != j) {
                const float* pi = &sp[(b*100 + i)*3];
                const float* pj = &sp[(b*100 + j)*3];
                float dx = pi[0]-pj[0], dy = pi[1]-pj[1], dz = pi[2]-pj[2];
                float dd = fmaf(dx, dx, fmaf(dy, dy, dz*dz));
                float rr = 0.01f - sqrtf(dd);
                if (rr > 0.f) sum += rr;
            }
        }
        block_add_to_acc(sum, 6);
    }
}

// ---------------------------------------------------------------- finalize
__global__ void final_kernel(float* out) {
    double cham   = g_acc[0] / (double)(B_*N_) + g_acc[1] / (double)(B_*M_);
    double emd    = g_acc[3] / (double)(NN*3) * 0.1;
    double cov    = g_acc[2] / (double)(B_*K_) * 5.0;
    double unif   = g_acc[4] / (double)NN * 2.0;
    double sstd   = g_acc[5] / 6.0;
    double spread = 0.5 - sstd;
    spread = (spread > 0.0) ? spread * 10.0 : 0.0;
    double rep    = g_acc[6] / (double)(B_*100*100) * 5.0;
    out[0] = (float)(cham + emd + cov + unif + spread + rep);
}

// ---------------------------------------------------------------- launch
// Critical path (stream 0): initpack -> rowmin_big -> uniformity -> unif_finish -> final.
// Side chain (s2, hides under uniformity): EMD sort/diff, cov rowmin,
// summin (after evA guarantees the big rowmins done), spreadrep.
extern "C" void kernel_launch(void* const* d_in, const int* in_sizes, int n_in,
                              void* d_out, int out_size) {
    const float* pred    = (const float*)d_in[0];
    const float* gt      = (const float*)d_in[1];
    const float* partial = (const float*)d_in[2];
    const int*   sidx    = (const int*)d_in[3];
    float* out = (float*)d_out;

    static cudaStream_t s2 = 0;
    static cudaEvent_t  evRoot = 0, evA = 0, ev2 = 0;
    if (s2 == 0) {
        cudaStreamCreateWithFlags(&s2, cudaStreamNonBlocking);
        cudaEventCreateWithFlags(&evRoot, cudaEventDisableTiming);
        cudaEventCreateWithFlags(&evA, cudaEventDisableTiming);
        cudaEventCreateWithFlags(&ev2, cudaEventDisableTiming);
    }

    initpack_kernel<<<32, 256>>>(pred);                                           // 1
    cudaEventRecord(evRoot, 0);
    cudaStreamWaitEvent(s2, evRoot, 0);

    rowmin_big_kernel<<<dim3(N_/256, 16, 2*B_), 128>>>(pred, gt);                 // 2
    cudaEventRecord(evA, 0);
    uniformity_kernel<<<(NN + UROWS - 1)/UROWS, 512>>>();                         // 3

    emd_sort_kernel<<<6, 1024, 0, s2>>>(pred, gt);                                // s2
    emd_diff_kernel<<<(3*NN+255)/256, 256, 0, s2>>>();                            // s2
    rowmin_kernel<<<dim3(K_/256, 16, B_), 128, 0, s2>>>(partial, pred, K_, N_, N_/16, 2);
    cudaStreamWaitEvent(s2, evA, 0);
    summin_all_kernel<<<80, 256, 0, s2>>>();
    spreadrep_kernel<<<7, 256, 0, s2>>>(pred, sidx);
    cudaEventRecord(ev2, s2);

    unif_finish_kernel<<<32, 256>>>();

    cudaStreamWaitEvent(0, ev2, 0);
    final_kernel<<<1, 1>>>(out);
}